// round 1
// baseline (speedup 1.0000x reference)
#include <cuda_runtime.h>
#include <cstdint>

// Problem constants (fixed by the reference):
//   x    : [B=8, N=50000, C=128] f32
//   cols : [M=25000, K=3] int32
//   vals : [M=25000, K=3] f32
//   out  : [B=8, M=25000, C=128] f32
// out[b,m,c] = sum_k vals[m,k] * x[b, cols[m,k], c]

#define B_DIM 8
#define N_DIM 50000
#define C_DIM 128
#define M_DIM 25000
#define K_DIM 3
#define MS_PER_BLOCK 2

__global__ __launch_bounds__(256, 8)
void mesh_sampling_kernel(const float* __restrict__ x,
                          const int*   __restrict__ cols,
                          const float* __restrict__ vals,
                          float*       __restrict__ out)
{
    const int warp = threadIdx.x >> 5;   // = batch index b (8 warps)
    const int lane = threadIdx.x & 31;   // owns channels [4*lane, 4*lane+4)
    const int m0   = blockIdx.x * MS_PER_BLOCK;

    const size_t x_b   = (size_t)warp * ((size_t)N_DIM * C_DIM);
    const size_t out_b = (size_t)warp * ((size_t)M_DIM * C_DIM);

#pragma unroll
    for (int mi = 0; mi < MS_PER_BLOCK; ++mi) {
        const int m = m0 + mi;
        if (m >= M_DIM) break;

        // Uniform (warp-broadcast) loads of indices & weights
        const int   c0 = __ldg(cols + (size_t)m * K_DIM + 0);
        const int   c1 = __ldg(cols + (size_t)m * K_DIM + 1);
        const int   c2 = __ldg(cols + (size_t)m * K_DIM + 2);
        const float v0 = __ldg(vals + (size_t)m * K_DIM + 0);
        const float v1 = __ldg(vals + (size_t)m * K_DIM + 1);
        const float v2 = __ldg(vals + (size_t)m * K_DIM + 2);

        const float4* __restrict__ p0 =
            (const float4*)(x + x_b + (size_t)c0 * C_DIM) + lane;
        const float4* __restrict__ p1 =
            (const float4*)(x + x_b + (size_t)c1 * C_DIM) + lane;
        const float4* __restrict__ p2 =
            (const float4*)(x + x_b + (size_t)c2 * C_DIM) + lane;

        const float4 a = __ldg(p0);
        const float4 b = __ldg(p1);
        const float4 c = __ldg(p2);

        float4 r;
        r.x = v0 * a.x + v1 * b.x + v2 * c.x;
        r.y = v0 * a.y + v1 * b.y + v2 * c.y;
        r.z = v0 * a.z + v1 * b.z + v2 * c.z;
        r.w = v0 * a.w + v1 * b.w + v2 * c.w;

        float4* __restrict__ po =
            (float4*)(out + out_b + (size_t)m * C_DIM) + lane;
        *po = r;
    }
}

extern "C" void kernel_launch(void* const* d_in, const int* in_sizes, int n_in,
                              void* d_out, int out_size)
{
    const float* x    = (const float*)d_in[0];
    const int*   cols = (const int*)  d_in[1];
    const float* vals = (const float*)d_in[2];
    float*       out  = (float*)      d_out;

    const int grid = (M_DIM + MS_PER_BLOCK - 1) / MS_PER_BLOCK;  // 12500
    mesh_sampling_kernel<<<grid, 256>>>(x, cols, vals, out);
}

// round 2
// speedup vs baseline: 1.2244x; 1.2244x over previous
#include <cuda_runtime.h>
#include <cstdint>

// Problem constants (fixed by the reference):
//   x    : [B=8, N=50000, C=128] f32
//   cols : [M=25000, K=3] int32
//   vals : [M=25000, K=3] f32
//   out  : [B=8, M=25000, C=128] f32
// out[b,m,c] = sum_k vals[m,k] * x[b, cols[m,k], c]
//
// Batch-major scheduling: blockIdx.y = b, so the chip sweeps one batch at a
// time and that batch's x slice (25.6 MB) stays L2-resident -> duplicate
// col indices across m hit L2 instead of DRAM.

#define B_DIM 8
#define N_DIM 50000
#define C_DIM 128
#define M_DIM 25000
#define K_DIM 3
#define MS_PER_WARP 2

__global__ __launch_bounds__(256, 8)
void mesh_sampling_kernel(const float* __restrict__ x,
                          const int*   __restrict__ cols,
                          const float* __restrict__ vals,
                          float*       __restrict__ out)
{
    const int b    = blockIdx.y;
    const int warp = threadIdx.x >> 5;
    const int lane = threadIdx.x & 31;   // owns channels [4*lane, 4*lane+4)

    // Each block covers 8 warps * MS_PER_WARP consecutive m's.
    const int m0 = (blockIdx.x * 8 + warp) * MS_PER_WARP;

    const float* __restrict__ xb   = x   + (size_t)b * ((size_t)N_DIM * C_DIM);
    float*       __restrict__ outb = out + (size_t)b * ((size_t)M_DIM * C_DIM);

#pragma unroll
    for (int mi = 0; mi < MS_PER_WARP; ++mi) {
        const int m = m0 + mi;
        if (m >= M_DIM) break;

        // Uniform (warp-broadcast) loads of indices & weights
        const int   c0 = __ldg(cols + (size_t)m * K_DIM + 0);
        const int   c1 = __ldg(cols + (size_t)m * K_DIM + 1);
        const int   c2 = __ldg(cols + (size_t)m * K_DIM + 2);
        const float v0 = __ldg(vals + (size_t)m * K_DIM + 0);
        const float v1 = __ldg(vals + (size_t)m * K_DIM + 1);
        const float v2 = __ldg(vals + (size_t)m * K_DIM + 2);

        const float4 a = __ldg((const float4*)(xb + (size_t)c0 * C_DIM) + lane);
        const float4 bb= __ldg((const float4*)(xb + (size_t)c1 * C_DIM) + lane);
        const float4 c = __ldg((const float4*)(xb + (size_t)c2 * C_DIM) + lane);

        float4 r;
        r.x = v0 * a.x + v1 * bb.x + v2 * c.x;
        r.y = v0 * a.y + v1 * bb.y + v2 * c.y;
        r.z = v0 * a.z + v1 * bb.z + v2 * c.z;
        r.w = v0 * a.w + v1 * bb.w + v2 * c.w;

        // Streaming store: evict-first so write-once output doesn't push
        // the L2-resident x slice out.
        __stcs((float4*)(outb + (size_t)m * C_DIM) + lane, r);
    }
}

extern "C" void kernel_launch(void* const* d_in, const int* in_sizes, int n_in,
                              void* d_out, int out_size)
{
    const float* x    = (const float*)d_in[0];
    const int*   cols = (const int*)  d_in[1];
    const float* vals = (const float*)d_in[2];
    float*       out  = (float*)      d_out;

    const int ms_per_block = 8 * MS_PER_WARP;                    // 16
    dim3 grid((M_DIM + ms_per_block - 1) / ms_per_block, B_DIM); // (1563, 8)
    mesh_sampling_kernel<<<grid, 256>>>(x, cols, vals, out);
}